// round 14
// baseline (speedup 1.0000x reference)
#include <cuda_runtime.h>
#include <cuda_fp16.h>
#include <math.h>
#include <stdint.h>

#define BB  4
#define NN  1024
#define DM_ 512
#define HH  8
#define CC  3
#define DC_ 16
#define DK_ 64
#define XW  (CC*DC_)
#define LOG2E 1.44269504088896340736f

// ---------------- device scratch (16B-aligned for vector ld/st) ------------
__device__ __align__(16) __half g_h16[(size_t)BB*NN*DM_];
__device__ __align__(16) __half g_Wq16[DM_*DM_];
__device__ __align__(16) __half g_Wk16[DM_*DM_];
__device__ __align__(16) __half g_Wv16[DM_*DM_];
__device__ __align__(16) __half g_Wo16[DM_*DM_];
__device__ __align__(16) __half g_Q16[(size_t)BB*HH*NN*DK_];
__device__ __align__(16) __half g_K16[(size_t)BB*HH*NN*DK_];
__device__ __align__(16) __half g_V16[(size_t)BB*HH*NN*DK_];
__device__ __align__(16) __half g_AO16[(size_t)BB*NN*DM_];
__device__ __align__(16) float  g_bias[(size_t)BB*HH*NN*NN];   // stores bias * log2(e)
__device__ __align__(16) float  g_sq[BB*NN*CC];
__device__ __align__(16) float  g_alpha[HH*CC];
__device__ __align__(16) float  g_gcoef[HH*CC];
__device__ int    g_uniform;

// ---------------- helpers ----------------
__device__ __forceinline__ uint32_t smem_u32(const void* p) {
    uint32_t a;
    asm("{ .reg .u64 t; cvta.to.shared.u64 t, %1; cvt.u32.u64 %0, t; }" : "=r"(a) : "l"(p));
    return a;
}
__device__ __forceinline__ uint32_t swz(uint32_t o) { return o ^ ((o >> 3) & 0x70); }

__device__ __forceinline__ void mma16816(float* d, const uint32_t* a, const uint32_t* b) {
    asm volatile("mma.sync.aligned.m16n8k16.row.col.f32.f16.f16.f32 "
        "{%0,%1,%2,%3}, {%4,%5,%6,%7}, {%8,%9}, {%0,%1,%2,%3};"
        : "+f"(d[0]), "+f"(d[1]), "+f"(d[2]), "+f"(d[3])
        : "r"(a[0]), "r"(a[1]), "r"(a[2]), "r"(a[3]), "r"(b[0]), "r"(b[1]));
}
__device__ __forceinline__ void ldm_x4(uint32_t* r, uint32_t addr) {
    asm volatile("ldmatrix.sync.aligned.m8n8.x4.shared.b16 {%0,%1,%2,%3}, [%4];"
        : "=r"(r[0]), "=r"(r[1]), "=r"(r[2]), "=r"(r[3]) : "r"(addr));
}
__device__ __forceinline__ void ldm_x4_t(uint32_t* r, uint32_t addr) {
    asm volatile("ldmatrix.sync.aligned.m8n8.x4.trans.shared.b16 {%0,%1,%2,%3}, [%4];"
        : "=r"(r[0]), "=r"(r[1]), "=r"(r[2]), "=r"(r[3]) : "r"(addr));
}
__device__ __forceinline__ void cp16(uint32_t saddr, const void* gptr) {
    asm volatile("cp.async.cg.shared.global [%0], [%1], 16;" :: "r"(saddr), "l"(gptr));
}
#define CP_COMMIT() asm volatile("cp.async.commit_group;" ::: "memory")
#define CP_WAIT1()  asm volatile("cp.async.wait_group 1;" ::: "memory")
#define CP_WAIT0()  asm volatile("cp.async.wait_group 0;" ::: "memory")

// ---------------- small prep kernels ----------------
__global__ void prep_coef_kernel(const float* __restrict__ alpha, const float* __restrict__ lsig) {
    int i = threadIdx.x;   // 32 threads, HH*CC = 24 live
    int ok = 1;
    if (i < HH*CC) {
        float a = alpha[i], l = lsig[i];
        float s = expf(l);
        if (s < 1e-4f) s = 1e-4f;
        g_gcoef[i] = 1.0f / (2.0f * s * s);
        g_alpha[i] = a;
        ok = (a == alpha[i % CC]) && (l == lsig[i % CC]);
    }
    int uni = __all_sync(0xffffffffu, ok);
    if (i == 0) g_uniform = uni;
}

__global__ void sq_kernel(const float* __restrict__ x) {
    int t = blockIdx.x * blockDim.x + threadIdx.x;
    if (t >= BB*NN*CC) return;
    int c = t % CC; int bn = t / CC;
    const float* p = x + (size_t)bn * XW + c * DC_;
    float s = 0.f;
#pragma unroll
    for (int d = 0; d < DC_; d++) s += p[d] * p[d];
    g_sq[t] = s;
}

// vectorized fp32 -> fp16 conversion: 8 elements per thread
__device__ __forceinline__ void cvt8(const float* __restrict__ src, __half* __restrict__ dst) {
    float4 a = *(const float4*)src;
    float4 b = *(const float4*)(src + 4);
    __half2 r[4];
    r[0] = __floats2half2_rn(a.x, a.y);
    r[1] = __floats2half2_rn(a.z, a.w);
    r[2] = __floats2half2_rn(b.x, b.y);
    r[3] = __floats2half2_rn(b.z, b.w);
    *(uint4*)dst = *(uint4*)r;
}

// h only (critical path, main stream)
__global__ void convert_h_kernel(const float* __restrict__ h) {
    int i = blockIdx.x * blockDim.x + threadIdx.x;
    if (i < BB*NN*DM_/8) cvt8(h + (size_t)i*8, g_h16 + (size_t)i*8);
}

// weights (side stream, hidden under main-stream work)
__global__ void convert_w_kernel(const float* __restrict__ wq, const float* __restrict__ wk,
                                 const float* __restrict__ wv, const float* __restrict__ wo) {
    int i = blockIdx.x * blockDim.x + threadIdx.x;
    if (i < DM_*DM_/8) {
        cvt8(wq + i*8, g_Wq16 + i*8);
        cvt8(wk + i*8, g_Wk16 + i*8);
        cvt8(wv + i*8, g_Wv16 + i*8);
        cvt8(wo + i*8, g_Wo16 + i*8);
    }
}

// ---------------- geodesic bias (fp32; output scaled by log2e) -------------
__global__ __launch_bounds__(256)
void bias_kernel(const float* __restrict__ x) {
    __shared__ float Xi[64][49];
    __shared__ float Xj[64][49];
    __shared__ float sqi[64][3];
    __shared__ float sqj[64][3];

    const int bh = blockIdx.z;
    const int h2 = bh & (HH-1);
    const int b2 = bh >> 3;
    if (g_uniform && h2 > 0) return;

    const int i0 = blockIdx.y * 64, j0 = blockIdx.x * 64;
    const int tid = threadIdx.x;
    const int tx = tid & 15, ty = tid >> 4;

    const float* xb = x + (size_t)b2 * NN * XW;
#pragma unroll
    for (int t = 0; t < 12; t++) {
        int idx = tid + t * 256;
        int row = idx / XW, col = idx % XW;
        Xi[row][col] = xb[(size_t)(i0 + row) * XW + col];
        Xj[row][col] = xb[(size_t)(j0 + row) * XW + col];
    }
    if (tid < 192) {
        int row = tid / 3, c = tid % 3;
        sqi[row][c] = g_sq[((size_t)b2 * NN + i0 + row) * CC + c];
        sqj[row][c] = g_sq[((size_t)b2 * NN + j0 + row) * CC + c];
    }
    __syncthreads();

    float Acf[CC], Gcf[CC];
#pragma unroll
    for (int c = 0; c < CC; c++) {
        Acf[c] = g_alpha[h2*CC + c] * LOG2E;   // fold log2e for base-2 softmax
        Gcf[c] = g_gcoef[h2*CC + c];
    }

    float* outp = g_bias + (size_t)(b2*HH + h2) * NN * NN;

#pragma unroll
    for (int r = 0; r < 4; r++) {
        int i = 4*ty + r;
        float4 res;
        float* resp = (float*)&res;
#pragma unroll
        for (int c = 0; c < 4; c++) {
            int j = 4*tx + c;
            float bsum = 0.f;
#pragma unroll
            for (int cm = 0; cm < CC; cm++) {
                float inner = 0.f;
#pragma unroll
                for (int d = 0; d < DC_; d++)
                    inner = fmaf(Xi[i][cm*DC_ + d], Xj[j][cm*DC_ + d], inner);
                float dd = fmaxf(sqi[i][cm] + sqj[j][cm] - 2.f * inner, 0.f);
                bsum = fmaf(Acf[cm], __expf(-dd * Gcf[cm]), bsum);
            }
            resp[c] = bsum;
        }
        *(float4*)(outp + (size_t)(i0 + i) * NN + j0 + 4*tx) = res;
    }
}

// ---------------- HMMA GEMM (128x128 block, K=512, cp.async 3-stage) -------
#define GSMEM 98304

__device__ __forceinline__ void gemm_load_stage(const __half* __restrict__ A,
                                                const __half* __restrict__ W,
                                                uint32_t sb, int m0, int o0,
                                                int kt, int stage, int tid) {
    const uint32_t base = sb + (uint32_t)stage * 32768u;
#pragma unroll
    for (int i = 0; i < 4; i++) {
        int idx = tid + i * 256, row = idx >> 3, seg = idx & 7;
        uint32_t sw = swz((uint32_t)(row * 128 + seg * 16));
        cp16(base + sw,          A + (size_t)(m0 + row) * DM_ + kt*64 + seg*8);
        cp16(base + 16384 + sw,  W + (size_t)(o0 + row) * DM_ + kt*64 + seg*8);
    }
}

__device__ __forceinline__ void hmma_mainloop(const __half* __restrict__ A,
                                              const __half* __restrict__ W,
                                              char* smem, int m0, int o0,
                                              float acc[4][4][4]) {
    const int tid = threadIdx.x;
    const int lane = tid & 31, wid = tid >> 5;
    const int wm = wid >> 2, wn = wid & 3;
    const uint32_t sb = smem_u32(smem);

    gemm_load_stage(A, W, sb, m0, o0, 0, 0, tid); CP_COMMIT();
    gemm_load_stage(A, W, sb, m0, o0, 1, 1, tid); CP_COMMIT();

    for (int kt = 0; kt < 8; kt++) {
        CP_WAIT1();
        __syncthreads();
        const uint32_t abase = sb + (uint32_t)(kt % 3) * 32768u;
        const uint32_t bbase = abase + 16384;
#pragma unroll
        for (int ks = 0; ks < 4; ks++) {
            uint32_t af[4][4];
#pragma unroll
            for (int mt = 0; mt < 4; mt++)
                ldm_x4(af[mt], abase + swz((uint32_t)((wm*64 + mt*16 + (lane & 15)) * 128
                                                      + ks*32 + ((lane >> 4) & 1) * 16)));
#pragma unroll
            for (int np = 0; np < 2; np++) {
                uint32_t bf[4];
                ldm_x4(bf, bbase + swz((uint32_t)((wn*32 + np*16 + (lane & 7) + ((lane >> 4) & 1)*8) * 128
                                                  + ks*32 + ((lane >> 3) & 1) * 16)));
#pragma unroll
                for (int mt = 0; mt < 4; mt++) {
                    mma16816(acc[mt][np*2],     af[mt], bf);
                    mma16816(acc[mt][np*2 + 1], af[mt], bf + 2);
                }
            }
        }
        if (kt < 6) gemm_load_stage(A, W, sb, m0, o0, kt + 2, (kt + 2) % 3, tid);
        CP_COMMIT();
    }
}

__global__ __launch_bounds__(256, 2)
void qkv_gemm(const float* __restrict__ bq, const float* __restrict__ bk, const float* __restrict__ bv) {
    extern __shared__ char smem[];
    const int z = blockIdx.z;
    const __half* W = (z == 0) ? g_Wq16 : ((z == 1) ? g_Wk16 : g_Wv16);
    const float* bias = (z == 0) ? bq : ((z == 1) ? bk : bv);
    __half* OUT = (z == 0) ? g_Q16 : ((z == 1) ? g_K16 : g_V16);
    // Q gets 1/sqrt(dk) * log2(e) folded in (base-2 softmax)
    const float scale = (z == 0) ? (0.125f * LOG2E) : 1.0f;
    const int m0 = blockIdx.y * 128, o0 = blockIdx.x * 128;

    float acc[4][4][4] = {};
    hmma_mainloop(g_h16, W, smem, m0, o0, acc);

    const int lane = threadIdx.x & 31, wid = threadIdx.x >> 5;
    const int wm = wid >> 2, wn = wid & 3;
    const int g = lane >> 2, t2 = (lane & 3) * 2;
#pragma unroll
    for (int mt = 0; mt < 4; mt++) {
#pragma unroll
        for (int nt = 0; nt < 4; nt++) {
            int o = o0 + wn*32 + nt*8 + t2;
            int hd = o >> 6, dk0 = o & 63;
            float b0 = bias[o], b1 = bias[o + 1];
#pragma unroll
            for (int half = 0; half < 2; half++) {
                int m = m0 + wm*64 + mt*16 + g + half*8;
                int b2 = m >> 10, n2 = m & 1023;
                float v0 = (acc[mt][nt][half*2]     + b0) * scale;
                float v1 = (acc[mt][nt][half*2 + 1] + b1) * scale;
                __half2 hh = __floats2half2_rn(v0, v1);
                *(__half2*)(OUT + (((size_t)(b2*HH + hd)) * NN + n2) * DK_ + dk0) = hh;
            }
        }
    }
}

__global__ __launch_bounds__(256, 2)
void out_gemm(const float* __restrict__ bo, float* __restrict__ out) {
    extern __shared__ char smem[];
    const int m0 = blockIdx.y * 128, o0 = blockIdx.x * 128;

    float acc[4][4][4] = {};
    hmma_mainloop(g_AO16, g_Wo16, smem, m0, o0, acc);

    const int lane = threadIdx.x & 31, wid = threadIdx.x >> 5;
    const int wm = wid >> 2, wn = wid & 3;
    const int g = lane >> 2, t2 = (lane & 3) * 2;
#pragma unroll
    for (int mt = 0; mt < 4; mt++) {
#pragma unroll
        for (int nt = 0; nt < 4; nt++) {
            int o = o0 + wn*32 + nt*8 + t2;
            float b0 = bo[o], b1 = bo[o + 1];
#pragma unroll
            for (int half = 0; half < 2; half++) {
                int m = m0 + wm*64 + mt*16 + g + half*8;
                float* dst = out + (size_t)m * DM_ + o;
                dst[0] = acc[mt][nt][half*2]     + b0;
                dst[1] = acc[mt][nt][half*2 + 1] + b1;
            }
        }
    }
}

// ---------------- HMMA flash attention (cp.async 2-stage K/V, 2 blk/SM) ----
#define ASMEM 81920

__device__ __forceinline__ void attn_load_kv(const __half* __restrict__ Kb,
                                             const __half* __restrict__ Vb,
                                             uint32_t sb, int j0, int stage, int tid) {
    const uint32_t kbase = sb + 16384u + (uint32_t)stage * 32768u;
#pragma unroll
    for (int i = 0; i < 4; i++) {
        int idx = tid + i * 256, row = idx >> 3, seg = idx & 7;
        uint32_t sw = swz((uint32_t)(row * 128 + seg * 16));
        cp16(kbase + sw,          Kb + (size_t)(j0 + row) * DK_ + seg * 8);
        cp16(kbase + 16384 + sw,  Vb + (size_t)(j0 + row) * DK_ + seg * 8);
    }
}

__global__ __launch_bounds__(256, 2)
void attn_hmma() {
    extern __shared__ char smem[];
    const uint32_t sb = smem_u32(smem);
    const int tid = threadIdx.x;
    const int lane = tid & 31, w = tid >> 5;
    const int g = lane >> 2, t2 = (lane & 3) * 2;

    const int bh = blockIdx.y;
    const int b2 = bh >> 3, h2 = bh & 7;
    const int i0 = blockIdx.x * 128;
    const int heff = g_uniform ? 0 : h2;

    const __half* Kb = g_K16 + (size_t)bh * NN * DK_;
    const __half* Vb = g_V16 + (size_t)bh * NN * DK_;

    attn_load_kv(Kb, Vb, sb, 0, 0, tid); CP_COMMIT();

    const __half* Qg = g_Q16 + ((size_t)bh * NN + i0) * DK_;
#pragma unroll
    for (int i = 0; i < 4; i++) {
        int idx = tid + i * 256, row = idx >> 3, seg = idx & 7;
        uint32_t sw = swz((uint32_t)(row * 128 + seg * 16));
        *(uint4*)(smem + sw) = *(const uint4*)(Qg + (size_t)row * DK_ + seg * 8);
    }
    __syncthreads();

    uint32_t qa[4][4];
#pragma unroll
    for (int ks = 0; ks < 4; ks++)
        ldm_x4(qa[ks], sb + swz((uint32_t)((w*16 + (lane & 15)) * 128
                                           + ks*32 + ((lane >> 4) & 1) * 16)));

    float m1 = -1e30f, m2 = -1e30f, l1 = 0.f, l2 = 0.f;
    float o_[8][4] = {};

    const float* Bg = g_bias + ((size_t)(b2*HH + heff) * NN + i0) * NN;

    for (int jt = 0; jt < 8; jt++) {
        const int j0 = jt * 128;
        CP_WAIT0();
        __syncthreads();
        if (jt < 7) { attn_load_kv(Kb, Vb, sb, (jt + 1) * 128, (jt + 1) & 1, tid); CP_COMMIT(); }

        const uint32_t KOFF = 16384u + (uint32_t)(jt & 1) * 32768u;
        const uint32_t VOFF = KOFF + 16384u;

        // init S accumulators with the geodesic bias (already in log2 units)
        float sf[16][4];
        const float* bp1 = Bg + (size_t)(16*w + g) * NN + j0 + t2;
        const float* bp2 = bp1 + 8 * NN;
#pragma unroll
        for (int nt = 0; nt < 16; nt++) {
            float2 bv1 = *(const float2*)(bp1 + nt*8);
            float2 bv2 = *(const float2*)(bp2 + nt*8);
            sf[nt][0] = bv1.x; sf[nt][1] = bv1.y;
            sf[nt][2] = bv2.x; sf[nt][3] = bv2.y;
        }

        // S = bias + Q @ K^T  (logits in base-2 units)
#pragma unroll
        for (int np = 0; np < 8; np++) {
#pragma unroll
            for (int ks = 0; ks < 4; ks++) {
                uint32_t bf[4];
                ldm_x4(bf, sb + KOFF + swz((uint32_t)((np*16 + (lane & 7) + ((lane >> 4) & 1)*8) * 128
                                                      + ks*32 + ((lane >> 3) & 1) * 16)));
                mma16816(sf[np*2],     qa[ks], bf);
                mma16816(sf[np*2 + 1], qa[ks], bf + 2);
            }
        }

        // row max (warp-local, rows g and g+8)
        float mx1 = sf[0][0], mx2 = sf[0][2];
#pragma unroll
        for (int nt = 0; nt < 16; nt++) {
            mx1 = fmaxf(mx1, fmaxf(sf[nt][0], sf[nt][1]));
            mx2 = fmaxf(mx2, fmaxf(sf[nt][2], sf[nt][3]));
        }
        mx1 = fmaxf(mx1, __shfl_xor_sync(0xffffffffu, mx1, 1));
        mx1 = fmaxf(mx1, __shfl_xor_sync(0xffffffffu, mx1, 2));
        mx2 = fmaxf(mx2, __shfl_xor_sync(0xffffffffu, mx2, 1));
        mx2 = fmaxf(mx2, __shfl_xor_sync(0xffffffffu, mx2, 2));

        float n1 = fmaxf(m1, mx1), n2 = fmaxf(m2, mx2);
        float f1 = exp2f(m1 - n1), f2 = exp2f(m2 - n2);
        m1 = n1; m2 = n2;

        // rescale O only when a factor actually changed (common fast path)
        if (f1 != 1.0f || f2 != 1.0f) {
#pragma unroll
            for (int dt = 0; dt < 8; dt++) {
                o_[dt][0] *= f1; o_[dt][1] *= f1;
                o_[dt][2] *= f2; o_[dt][3] *= f2;
            }
        }

        // exp (MUFU) interleaved with PV MMA (tensor) per k16 chunk
        float rs1 = 0.f, rs2 = 0.f;
#pragma unroll
        for (int kk = 0; kk < 8; kk++) {
            float e00 = exp2f(sf[2*kk][0]   - n1), e01 = exp2f(sf[2*kk][1]   - n1);
            float e02 = exp2f(sf[2*kk][2]   - n2), e03 = exp2f(sf[2*kk][3]   - n2);
            float e10 = exp2f(sf[2*kk+1][0] - n1), e11 = exp2f(sf[2*kk+1][1] - n1);
            float e12 = exp2f(sf[2*kk+1][2] - n2), e13 = exp2f(sf[2*kk+1][3] - n2);
            rs1 += e00 + e01 + e10 + e11;
            rs2 += e02 + e03 + e12 + e13;

            uint32_t pa[4];
            {
                __half2 h0 = __floats2half2_rn(e00, e01);
                __half2 h1 = __floats2half2_rn(e02, e03);
                __half2 h2_ = __floats2half2_rn(e10, e11);
                __half2 h3 = __floats2half2_rn(e12, e13);
                pa[0] = *(uint32_t*)&h0; pa[1] = *(uint32_t*)&h1;
                pa[2] = *(uint32_t*)&h2_; pa[3] = *(uint32_t*)&h3;
            }
#pragma unroll
            for (int dp = 0; dp < 4; dp++) {
                uint32_t bf[4];
                ldm_x4_t(bf, sb + VOFF + swz((uint32_t)((kk*16 + (lane & 7) + ((lane >> 3) & 1)*8) * 128
                                                        + dp*32 + ((lane >> 4) & 1) * 16)));
                mma16816(o_[dp*2],     pa, bf);
                mma16816(o_[dp*2 + 1], pa, bf + 2);
            }
        }

        // row-sum reduction after PV (off the critical MUFU->tensor path)
        rs1 += __shfl_xor_sync(0xffffffffu, rs1, 1);
        rs1 += __shfl_xor_sync(0xffffffffu, rs1, 2);
        rs2 += __shfl_xor_sync(0xffffffffu, rs2, 1);
        rs2 += __shfl_xor_sync(0xffffffffu, rs2, 2);
        l1 = l1 * f1 + rs1;
        l2 = l2 * f2 + rs2;
    }

    // epilogue
    float i1 = 1.0f / l1, i2 = 1.0f / l2;
    __half* dst1 = g_AO16 + ((size_t)b2 * NN + i0 + 16*w + g)     * DM_ + h2*DK_ + t2;
    __half* dst2 = g_AO16 + ((size_t)b2 * NN + i0 + 16*w + g + 8) * DM_ + h2*DK_ + t2;
#pragma unroll
    for (int dt = 0; dt < 8; dt++) {
        *(__half2*)(dst1 + dt*8) = __floats2half2_rn(o_[dt][0] * i1, o_[dt][1] * i1);
        *(__half2*)(dst2 + dt*8) = __floats2half2_rn(o_[dt][2] * i2, o_[dt][3] * i2);
    }
}

// ---------------- launcher ----------------
extern "C" void kernel_launch(void* const* d_in, const int* in_sizes, int n_in,
                              void* d_out, int out_size) {
    const float* h    = (const float*)d_in[0];
    const float* x    = (const float*)d_in[1];
    const float* Wq   = (const float*)d_in[2];
    const float* bq   = (const float*)d_in[3];
    const float* Wk   = (const float*)d_in[4];
    const float* bk   = (const float*)d_in[5];
    const float* Wv   = (const float*)d_in[6];
    const float* bv   = (const float*)d_in[7];
    const float* Wo   = (const float*)d_in[8];
    const float* bo   = (const float*)d_in[9];
    const float* alpha= (const float*)d_in[10];
    const float* lsig = (const float*)d_in[11];
    float* out = (float*)d_out;

    static cudaStream_t s2 = nullptr;
    static cudaEvent_t evFork = nullptr, evJoinW = nullptr, evJoinB = nullptr;
    if (s2 == nullptr) {
        cudaStreamCreateWithFlags(&s2, cudaStreamNonBlocking);
        cudaEventCreateWithFlags(&evFork, cudaEventDisableTiming);
        cudaEventCreateWithFlags(&evJoinW, cudaEventDisableTiming);
        cudaEventCreateWithFlags(&evJoinB, cudaEventDisableTiming);
    }

    cudaFuncSetAttribute(qkv_gemm, cudaFuncAttributeMaxDynamicSharedMemorySize, GSMEM);
    cudaFuncSetAttribute(out_gemm, cudaFuncAttributeMaxDynamicSharedMemorySize, GSMEM);
    cudaFuncSetAttribute(attn_hmma, cudaFuncAttributeMaxDynamicSharedMemorySize, ASMEM);

    // fork: side stream converts weights, then runs the bias chain
    cudaEventRecord(evFork, 0);
    cudaStreamWaitEvent(s2, evFork, 0);
    convert_w_kernel<<<(DM_*DM_/8 + 255)/256, 256, 0, s2>>>(Wq, Wk, Wv, Wo);
    cudaEventRecord(evJoinW, s2);     // weights ready
    prep_coef_kernel<<<1, 32, 0, s2>>>(alpha, lsig);
    sq_kernel<<<(BB*NN*CC + 127)/128, 128, 0, s2>>>(x);
    bias_kernel<<<dim3(NN/64, NN/64, BB*HH), 256, 0, s2>>>(x);
    cudaEventRecord(evJoinB, s2);     // bias + uniform flag ready

    // main stream: h conversion (critical path), then QKV (needs weights)
    convert_h_kernel<<<(BB*NN*DM_/8 + 255)/256, 256>>>(h);
    cudaStreamWaitEvent(0, evJoinW, 0);
    qkv_gemm<<<dim3(DM_/128, (BB*NN)/128, 3), 256, GSMEM>>>(bq, bk, bv);

    cudaStreamWaitEvent(0, evJoinB, 0);
    attn_hmma<<<dim3(NN/128, BB*HH), 256, ASMEM>>>();

    out_gemm<<<dim3(DM_/128, (BB*NN)/128), 256, GSMEM>>>(bo, out);
}

// round 15
// speedup vs baseline: 1.1497x; 1.1497x over previous
#include <cuda_runtime.h>
#include <cuda_fp16.h>
#include <math.h>
#include <stdint.h>

#define BB  4
#define NN  1024
#define DM_ 512
#define HH  8
#define CC  3
#define DC_ 16
#define DK_ 64
#define XW  (CC*DC_)
#define LOG2E 1.44269504088896340736f

// ---------------- device scratch (16B-aligned for vector ld/st) ------------
__device__ __align__(16) __half g_h16[(size_t)BB*NN*DM_];
__device__ __align__(16) __half g_Wq16[DM_*DM_];
__device__ __align__(16) __half g_Wk16[DM_*DM_];
__device__ __align__(16) __half g_Wv16[DM_*DM_];
__device__ __align__(16) __half g_Wo16[DM_*DM_];
__device__ __align__(16) __half g_Q16[(size_t)BB*HH*NN*DK_];
__device__ __align__(16) __half g_K16[(size_t)BB*HH*NN*DK_];
__device__ __align__(16) __half g_V16[(size_t)BB*HH*NN*DK_];
__device__ __align__(16) __half g_AO16[(size_t)BB*NN*DM_];
__device__ __align__(16) float  g_bias[(size_t)BB*HH*NN*NN];   // stores bias * log2(e)
__device__ __align__(16) float  g_sq[BB*NN*CC];
__device__ __align__(16) float  g_alpha[HH*CC];
__device__ __align__(16) float  g_gcoef[HH*CC];
__device__ int    g_uniform;

// ---------------- helpers ----------------
__device__ __forceinline__ uint32_t smem_u32(const void* p) {
    uint32_t a;
    asm("{ .reg .u64 t; cvta.to.shared.u64 t, %1; cvt.u32.u64 %0, t; }" : "=r"(a) : "l"(p));
    return a;
}
__device__ __forceinline__ uint32_t swz(uint32_t o) { return o ^ ((o >> 3) & 0x70); }

__device__ __forceinline__ void mma16816(float* d, const uint32_t* a, const uint32_t* b) {
    asm volatile("mma.sync.aligned.m16n8k16.row.col.f32.f16.f16.f32 "
        "{%0,%1,%2,%3}, {%4,%5,%6,%7}, {%8,%9}, {%0,%1,%2,%3};"
        : "+f"(d[0]), "+f"(d[1]), "+f"(d[2]), "+f"(d[3])
        : "r"(a[0]), "r"(a[1]), "r"(a[2]), "r"(a[3]), "r"(b[0]), "r"(b[1]));
}
__device__ __forceinline__ void ldm_x4(uint32_t* r, uint32_t addr) {
    asm volatile("ldmatrix.sync.aligned.m8n8.x4.shared.b16 {%0,%1,%2,%3}, [%4];"
        : "=r"(r[0]), "=r"(r[1]), "=r"(r[2]), "=r"(r[3]) : "r"(addr));
}
__device__ __forceinline__ void ldm_x4_t(uint32_t* r, uint32_t addr) {
    asm volatile("ldmatrix.sync.aligned.m8n8.x4.trans.shared.b16 {%0,%1,%2,%3}, [%4];"
        : "=r"(r[0]), "=r"(r[1]), "=r"(r[2]), "=r"(r[3]) : "r"(addr));
}
__device__ __forceinline__ void cp16(uint32_t saddr, const void* gptr) {
    asm volatile("cp.async.cg.shared.global [%0], [%1], 16;" :: "r"(saddr), "l"(gptr));
}
#define CP_COMMIT() asm volatile("cp.async.commit_group;" ::: "memory")
#define CP_WAIT1()  asm volatile("cp.async.wait_group 1;" ::: "memory")
#define CP_WAIT0()  asm volatile("cp.async.wait_group 0;" ::: "memory")

// ---------------- small prep kernels ----------------
__global__ void prep_coef_kernel(const float* __restrict__ alpha, const float* __restrict__ lsig) {
    int i = threadIdx.x;   // 32 threads, HH*CC = 24 live
    int ok = 1;
    if (i < HH*CC) {
        float a = alpha[i], l = lsig[i];
        float s = expf(l);
        if (s < 1e-4f) s = 1e-4f;
        g_gcoef[i] = 1.0f / (2.0f * s * s);
        g_alpha[i] = a;
        ok = (a == alpha[i % CC]) && (l == lsig[i % CC]);
    }
    int uni = __all_sync(0xffffffffu, ok);
    if (i == 0) g_uniform = uni;
}

__global__ void sq_kernel(const float* __restrict__ x) {
    int t = blockIdx.x * blockDim.x + threadIdx.x;
    if (t >= BB*NN*CC) return;
    int c = t % CC; int bn = t / CC;
    const float* p = x + (size_t)bn * XW + c * DC_;
    float s = 0.f;
#pragma unroll
    for (int d = 0; d < DC_; d++) s += p[d] * p[d];
    g_sq[t] = s;
}

// vectorized fp32 -> fp16 conversion: 8 elements per thread
__device__ __forceinline__ void cvt8(const float* __restrict__ src, __half* __restrict__ dst) {
    float4 a = *(const float4*)src;
    float4 b = *(const float4*)(src + 4);
    __half2 r[4];
    r[0] = __floats2half2_rn(a.x, a.y);
    r[1] = __floats2half2_rn(a.z, a.w);
    r[2] = __floats2half2_rn(b.x, b.y);
    r[3] = __floats2half2_rn(b.z, b.w);
    *(uint4*)dst = *(uint4*)r;
}

// h only (critical path, main stream)
__global__ void convert_h_kernel(const float* __restrict__ h) {
    int i = blockIdx.x * blockDim.x + threadIdx.x;
    if (i < BB*NN*DM_/8) cvt8(h + (size_t)i*8, g_h16 + (size_t)i*8);
}

// weights (side stream, hidden under main-stream work)
__global__ void convert_w_kernel(const float* __restrict__ wq, const float* __restrict__ wk,
                                 const float* __restrict__ wv, const float* __restrict__ wo) {
    int i = blockIdx.x * blockDim.x + threadIdx.x;
    if (i < DM_*DM_/8) {
        cvt8(wq + i*8, g_Wq16 + i*8);
        cvt8(wk + i*8, g_Wk16 + i*8);
        cvt8(wv + i*8, g_Wv16 + i*8);
        cvt8(wo + i*8, g_Wo16 + i*8);
    }
}

// ---------------- geodesic bias (fp32; output scaled by log2e) -------------
// Outer-product structure per manifold component; register-bounded.
__global__ __launch_bounds__(256, 3)
void bias_kernel(const float* __restrict__ x) {
    __shared__ float Xi[64][49];
    __shared__ float Xj[64][49];
    __shared__ float sqi[64][3];
    __shared__ float sqj[64][3];

    const int bh = blockIdx.z;
    const int h2 = bh & (HH-1);
    const int b2 = bh >> 3;
    if (g_uniform && h2 > 0) return;

    const int i0 = blockIdx.y * 64, j0 = blockIdx.x * 64;
    const int tid = threadIdx.x;
    const int tx = tid & 15, ty = tid >> 4;

    const float* xb = x + (size_t)b2 * NN * XW;
#pragma unroll
    for (int t = 0; t < 12; t++) {
        int idx = tid + t * 256;
        int row = idx / XW, col = idx % XW;
        Xi[row][col] = xb[(size_t)(i0 + row) * XW + col];
        Xj[row][col] = xb[(size_t)(j0 + row) * XW + col];
    }
    if (tid < 192) {
        int row = tid / 3, c = tid % 3;
        sqi[row][c] = g_sq[((size_t)b2 * NN + i0 + row) * CC + c];
        sqj[row][c] = g_sq[((size_t)b2 * NN + j0 + row) * CC + c];
    }
    __syncthreads();

    float bsum[4][4] = {};

#pragma unroll
    for (int cm = 0; cm < CC; cm++) {
        // alpha scaled by log2e (base-2 softmax); gamma scaled by log2e (exp2)
        const float A = g_alpha[h2*CC + cm] * LOG2E;
        const float G = g_gcoef[h2*CC + cm] * LOG2E;

        float inner[4][4] = {};
#pragma unroll
        for (int d = 0; d < DC_; d++) {
            float xi[4], xj[4];
#pragma unroll
            for (int r = 0; r < 4; r++) xi[r] = Xi[4*ty + r][cm*DC_ + d];
#pragma unroll
            for (int c = 0; c < 4; c++) xj[c] = Xj[4*tx + c][cm*DC_ + d];
#pragma unroll
            for (int r = 0; r < 4; r++)
#pragma unroll
                for (int c = 0; c < 4; c++)
                    inner[r][c] = fmaf(xi[r], xj[c], inner[r][c]);
        }
#pragma unroll
        for (int r = 0; r < 4; r++) {
            float si = sqi[4*ty + r][cm];
#pragma unroll
            for (int c = 0; c < 4; c++) {
                float dd = fmaxf(si + sqj[4*tx + c][cm] - 2.f * inner[r][c], 0.f);
                bsum[r][c] = fmaf(A, exp2f(-dd * G), bsum[r][c]);
            }
        }
    }

    float* outp = g_bias + (size_t)(b2*HH + h2) * NN * NN;
#pragma unroll
    for (int r = 0; r < 4; r++) {
        float4 res = make_float4(bsum[r][0], bsum[r][1], bsum[r][2], bsum[r][3]);
        *(float4*)(outp + (size_t)(i0 + 4*ty + r) * NN + j0 + 4*tx) = res;
    }
}

// ---------------- HMMA GEMM (128x128 block, K=512, cp.async 3-stage) -------
#define GSMEM 98304

__device__ __forceinline__ void gemm_load_stage(const __half* __restrict__ A,
                                                const __half* __restrict__ W,
                                                uint32_t sb, int m0, int o0,
                                                int kt, int stage, int tid) {
    const uint32_t base = sb + (uint32_t)stage * 32768u;
#pragma unroll
    for (int i = 0; i < 4; i++) {
        int idx = tid + i * 256, row = idx >> 3, seg = idx & 7;
        uint32_t sw = swz((uint32_t)(row * 128 + seg * 16));
        cp16(base + sw,          A + (size_t)(m0 + row) * DM_ + kt*64 + seg*8);
        cp16(base + 16384 + sw,  W + (size_t)(o0 + row) * DM_ + kt*64 + seg*8);
    }
}

__device__ __forceinline__ void hmma_mainloop(const __half* __restrict__ A,
                                              const __half* __restrict__ W,
                                              char* smem, int m0, int o0,
                                              float acc[4][4][4]) {
    const int tid = threadIdx.x;
    const int lane = tid & 31, wid = tid >> 5;
    const int wm = wid >> 2, wn = wid & 3;
    const uint32_t sb = smem_u32(smem);

    gemm_load_stage(A, W, sb, m0, o0, 0, 0, tid); CP_COMMIT();
    gemm_load_stage(A, W, sb, m0, o0, 1, 1, tid); CP_COMMIT();

    for (int kt = 0; kt < 8; kt++) {
        CP_WAIT1();
        __syncthreads();
        const uint32_t abase = sb + (uint32_t)(kt % 3) * 32768u;
        const uint32_t bbase = abase + 16384;
#pragma unroll
        for (int ks = 0; ks < 4; ks++) {
            uint32_t af[4][4];
#pragma unroll
            for (int mt = 0; mt < 4; mt++)
                ldm_x4(af[mt], abase + swz((uint32_t)((wm*64 + mt*16 + (lane & 15)) * 128
                                                      + ks*32 + ((lane >> 4) & 1) * 16)));
#pragma unroll
            for (int np = 0; np < 2; np++) {
                uint32_t bf[4];
                ldm_x4(bf, bbase + swz((uint32_t)((wn*32 + np*16 + (lane & 7) + ((lane >> 4) & 1)*8) * 128
                                                  + ks*32 + ((lane >> 3) & 1) * 16)));
#pragma unroll
                for (int mt = 0; mt < 4; mt++) {
                    mma16816(acc[mt][np*2],     af[mt], bf);
                    mma16816(acc[mt][np*2 + 1], af[mt], bf + 2);
                }
            }
        }
        if (kt < 6) gemm_load_stage(A, W, sb, m0, o0, kt + 2, (kt + 2) % 3, tid);
        CP_COMMIT();
    }
}

__global__ __launch_bounds__(256, 2)
void qkv_gemm(const float* __restrict__ bq, const float* __restrict__ bk, const float* __restrict__ bv) {
    extern __shared__ char smem[];
    const int z = blockIdx.z;
    const __half* W = (z == 0) ? g_Wq16 : ((z == 1) ? g_Wk16 : g_Wv16);
    const float* bias = (z == 0) ? bq : ((z == 1) ? bk : bv);
    __half* OUT = (z == 0) ? g_Q16 : ((z == 1) ? g_K16 : g_V16);
    // Q gets 1/sqrt(dk) * log2(e) folded in (base-2 softmax)
    const float scale = (z == 0) ? (0.125f * LOG2E) : 1.0f;
    const int m0 = blockIdx.y * 128, o0 = blockIdx.x * 128;

    float acc[4][4][4] = {};
    hmma_mainloop(g_h16, W, smem, m0, o0, acc);

    const int lane = threadIdx.x & 31, wid = threadIdx.x >> 5;
    const int wm = wid >> 2, wn = wid & 3;
    const int g = lane >> 2, t2 = (lane & 3) * 2;
#pragma unroll
    for (int mt = 0; mt < 4; mt++) {
#pragma unroll
        for (int nt = 0; nt < 4; nt++) {
            int o = o0 + wn*32 + nt*8 + t2;
            int hd = o >> 6, dk0 = o & 63;
            float b0 = bias[o], b1 = bias[o + 1];
#pragma unroll
            for (int half = 0; half < 2; half++) {
                int m = m0 + wm*64 + mt*16 + g + half*8;
                int b2 = m >> 10, n2 = m & 1023;
                float v0 = (acc[mt][nt][half*2]     + b0) * scale;
                float v1 = (acc[mt][nt][half*2 + 1] + b1) * scale;
                __half2 hh = __floats2half2_rn(v0, v1);
                *(__half2*)(OUT + (((size_t)(b2*HH + hd)) * NN + n2) * DK_ + dk0) = hh;
            }
        }
    }
}

__global__ __launch_bounds__(256, 2)
void out_gemm(const float* __restrict__ bo, float* __restrict__ out) {
    extern __shared__ char smem[];
    const int m0 = blockIdx.y * 128, o0 = blockIdx.x * 128;

    float acc[4][4][4] = {};
    hmma_mainloop(g_AO16, g_Wo16, smem, m0, o0, acc);

    const int lane = threadIdx.x & 31, wid = threadIdx.x >> 5;
    const int wm = wid >> 2, wn = wid & 3;
    const int g = lane >> 2, t2 = (lane & 3) * 2;
#pragma unroll
    for (int mt = 0; mt < 4; mt++) {
#pragma unroll
        for (int nt = 0; nt < 4; nt++) {
            int o = o0 + wn*32 + nt*8 + t2;
            float b0 = bo[o], b1 = bo[o + 1];
#pragma unroll
            for (int half = 0; half < 2; half++) {
                int m = m0 + wm*64 + mt*16 + g + half*8;
                float* dst = out + (size_t)m * DM_ + o;
                dst[0] = acc[mt][nt][half*2]     + b0;
                dst[1] = acc[mt][nt][half*2 + 1] + b1;
            }
        }
    }
}

// ---------------- HMMA flash attention (cp.async 2-stage K/V, 2 blk/SM) ----
#define ASMEM 81920

__device__ __forceinline__ void attn_load_kv(const __half* __restrict__ Kb,
                                             const __half* __restrict__ Vb,
                                             uint32_t sb, int j0, int stage, int tid) {
    const uint32_t kbase = sb + 16384u + (uint32_t)stage * 32768u;
#pragma unroll
    for (int i = 0; i < 4; i++) {
        int idx = tid + i * 256, row = idx >> 3, seg = idx & 7;
        uint32_t sw = swz((uint32_t)(row * 128 + seg * 16));
        cp16(kbase + sw,          Kb + (size_t)(j0 + row) * DK_ + seg * 8);
        cp16(kbase + 16384 + sw,  Vb + (size_t)(j0 + row) * DK_ + seg * 8);
    }
}

__global__ __launch_bounds__(256, 2)
void attn_hmma() {
    extern __shared__ char smem[];
    const uint32_t sb = smem_u32(smem);
    const int tid = threadIdx.x;
    const int lane = tid & 31, w = tid >> 5;
    const int g = lane >> 2, t2 = (lane & 3) * 2;

    const int bh = blockIdx.y;
    const int b2 = bh >> 3, h2 = bh & 7;
    const int i0 = blockIdx.x * 128;
    const int heff = g_uniform ? 0 : h2;

    const __half* Kb = g_K16 + (size_t)bh * NN * DK_;
    const __half* Vb = g_V16 + (size_t)bh * NN * DK_;

    attn_load_kv(Kb, Vb, sb, 0, 0, tid); CP_COMMIT();

    const __half* Qg = g_Q16 + ((size_t)bh * NN + i0) * DK_;
#pragma unroll
    for (int i = 0; i < 4; i++) {
        int idx = tid + i * 256, row = idx >> 3, seg = idx & 7;
        uint32_t sw = swz((uint32_t)(row * 128 + seg * 16));
        *(uint4*)(smem + sw) = *(const uint4*)(Qg + (size_t)row * DK_ + seg * 8);
    }
    __syncthreads();

    uint32_t qa[4][4];
#pragma unroll
    for (int ks = 0; ks < 4; ks++)
        ldm_x4(qa[ks], sb + swz((uint32_t)((w*16 + (lane & 15)) * 128
                                           + ks*32 + ((lane >> 4) & 1) * 16)));

    float m1 = -1e30f, m2 = -1e30f, l1 = 0.f, l2 = 0.f;
    float o_[8][4] = {};

    const float* Bg = g_bias + ((size_t)(b2*HH + heff) * NN + i0) * NN;

    for (int jt = 0; jt < 8; jt++) {
        const int j0 = jt * 128;
        CP_WAIT0();
        __syncthreads();
        if (jt < 7) { attn_load_kv(Kb, Vb, sb, (jt + 1) * 128, (jt + 1) & 1, tid); CP_COMMIT(); }

        const uint32_t KOFF = 16384u + (uint32_t)(jt & 1) * 32768u;
        const uint32_t VOFF = KOFF + 16384u;

        // init S accumulators with the geodesic bias (already in log2 units)
        float sf[16][4];
        const float* bp1 = Bg + (size_t)(16*w + g) * NN + j0 + t2;
        const float* bp2 = bp1 + 8 * NN;
#pragma unroll
        for (int nt = 0; nt < 16; nt++) {
            float2 bv1 = *(const float2*)(bp1 + nt*8);
            float2 bv2 = *(const float2*)(bp2 + nt*8);
            sf[nt][0] = bv1.x; sf[nt][1] = bv1.y;
            sf[nt][2] = bv2.x; sf[nt][3] = bv2.y;
        }

        // S = bias + Q @ K^T  (logits in base-2 units)
#pragma unroll
        for (int np = 0; np < 8; np++) {
#pragma unroll
            for (int ks = 0; ks < 4; ks++) {
                uint32_t bf[4];
                ldm_x4(bf, sb + KOFF + swz((uint32_t)((np*16 + (lane & 7) + ((lane >> 4) & 1)*8) * 128
                                                      + ks*32 + ((lane >> 3) & 1) * 16)));
                mma16816(sf[np*2],     qa[ks], bf);
                mma16816(sf[np*2 + 1], qa[ks], bf + 2);
            }
        }

        // row max (warp-local, rows g and g+8)
        float mx1 = sf[0][0], mx2 = sf[0][2];
#pragma unroll
        for (int nt = 0; nt < 16; nt++) {
            mx1 = fmaxf(mx1, fmaxf(sf[nt][0], sf[nt][1]));
            mx2 = fmaxf(mx2, fmaxf(sf[nt][2], sf[nt][3]));
        }
        mx1 = fmaxf(mx1, __shfl_xor_sync(0xffffffffu, mx1, 1));
        mx1 = fmaxf(mx1, __shfl_xor_sync(0xffffffffu, mx1, 2));
        mx2 = fmaxf(mx2, __shfl_xor_sync(0xffffffffu, mx2, 1));
        mx2 = fmaxf(mx2, __shfl_xor_sync(0xffffffffu, mx2, 2));

        float n1 = fmaxf(m1, mx1), n2 = fmaxf(m2, mx2);
        float f1 = exp2f(m1 - n1), f2 = exp2f(m2 - n2);
        m1 = n1; m2 = n2;

        // rescale O only when a factor actually changed (common fast path)
        if (f1 != 1.0f || f2 != 1.0f) {
#pragma unroll
            for (int dt = 0; dt < 8; dt++) {
                o_[dt][0] *= f1; o_[dt][1] *= f1;
                o_[dt][2] *= f2; o_[dt][3] *= f2;
            }
        }

        // exp (MUFU) interleaved with PV MMA (tensor) per k16 chunk
        float rs1 = 0.f, rs2 = 0.f;
#pragma unroll
        for (int kk = 0; kk < 8; kk++) {
            float e00 = exp2f(sf[2*kk][0]   - n1), e01 = exp2f(sf[2*kk][1]   - n1);
            float e02 = exp2f(sf[2*kk][2]   - n2), e03 = exp2f(sf[2*kk][3]   - n2);
            float e10 = exp2f(sf[2*kk+1][0] - n1), e11 = exp2f(sf[2*kk+1][1] - n1);
            float e12 = exp2f(sf[2*kk+1][2] - n2), e13 = exp2f(sf[2*kk+1][3] - n2);
            rs1 += e00 + e01 + e10 + e11;
            rs2 += e02 + e03 + e12 + e13;

            uint32_t pa[4];
            {
                __half2 h0 = __floats2half2_rn(e00, e01);
                __half2 h1 = __floats2half2_rn(e02, e03);
                __half2 h2_ = __floats2half2_rn(e10, e11);
                __half2 h3 = __floats2half2_rn(e12, e13);
                pa[0] = *(uint32_t*)&h0; pa[1] = *(uint32_t*)&h1;
                pa[2] = *(uint32_t*)&h2_; pa[3] = *(uint32_t*)&h3;
            }
#pragma unroll
            for (int dp = 0; dp < 4; dp++) {
                uint32_t bf[4];
                ldm_x4_t(bf, sb + VOFF + swz((uint32_t)((kk*16 + (lane & 7) + ((lane >> 3) & 1)*8) * 128
                                                        + dp*32 + ((lane >> 4) & 1) * 16)));
                mma16816(o_[dp*2],     pa, bf);
                mma16816(o_[dp*2 + 1], pa, bf + 2);
            }
        }

        // row-sum reduction after PV (off the critical MUFU->tensor path)
        rs1 += __shfl_xor_sync(0xffffffffu, rs1, 1);
        rs1 += __shfl_xor_sync(0xffffffffu, rs1, 2);
        rs2 += __shfl_xor_sync(0xffffffffu, rs2, 1);
        rs2 += __shfl_xor_sync(0xffffffffu, rs2, 2);
        l1 = l1 * f1 + rs1;
        l2 = l2 * f2 + rs2;
    }

    // epilogue
    float i1 = 1.0f / l1, i2 = 1.0f / l2;
    __half* dst1 = g_AO16 + ((size_t)b2 * NN + i0 + 16*w + g)     * DM_ + h2*DK_ + t2;
    __half* dst2 = g_AO16 + ((size_t)b2 * NN + i0 + 16*w + g + 8) * DM_ + h2*DK_ + t2;
#pragma unroll
    for (int dt = 0; dt < 8; dt++) {
        *(__half2*)(dst1 + dt*8) = __floats2half2_rn(o_[dt][0] * i1, o_[dt][1] * i1);
        *(__half2*)(dst2 + dt*8) = __floats2half2_rn(o_[dt][2] * i2, o_[dt][3] * i2);
    }
}

// ---------------- launcher ----------------
extern "C" void kernel_launch(void* const* d_in, const int* in_sizes, int n_in,
                              void* d_out, int out_size) {
    const float* h    = (const float*)d_in[0];
    const float* x    = (const float*)d_in[1];
    const float* Wq   = (const float*)d_in[2];
    const float* bq   = (const float*)d_in[3];
    const float* Wk   = (const float*)d_in[4];
    const float* bk   = (const float*)d_in[5];
    const float* Wv   = (const float*)d_in[6];
    const float* bv   = (const float*)d_in[7];
    const float* Wo   = (const float*)d_in[8];
    const float* bo   = (const float*)d_in[9];
    const float* alpha= (const float*)d_in[10];
    const float* lsig = (const float*)d_in[11];
    float* out = (float*)d_out;

    static cudaStream_t s2 = nullptr;
    static cudaEvent_t evFork = nullptr, evJoinW = nullptr, evJoinB = nullptr;
    if (s2 == nullptr) {
        cudaStreamCreateWithFlags(&s2, cudaStreamNonBlocking);
        cudaEventCreateWithFlags(&evFork, cudaEventDisableTiming);
        cudaEventCreateWithFlags(&evJoinW, cudaEventDisableTiming);
        cudaEventCreateWithFlags(&evJoinB, cudaEventDisableTiming);
    }

    cudaFuncSetAttribute(qkv_gemm, cudaFuncAttributeMaxDynamicSharedMemorySize, GSMEM);
    cudaFuncSetAttribute(out_gemm, cudaFuncAttributeMaxDynamicSharedMemorySize, GSMEM);
    cudaFuncSetAttribute(attn_hmma, cudaFuncAttributeMaxDynamicSharedMemorySize, ASMEM);

    // fork: side stream converts weights, then runs the bias chain
    cudaEventRecord(evFork, 0);
    cudaStreamWaitEvent(s2, evFork, 0);
    convert_w_kernel<<<(DM_*DM_/8 + 255)/256, 256, 0, s2>>>(Wq, Wk, Wv, Wo);
    cudaEventRecord(evJoinW, s2);     // weights ready
    prep_coef_kernel<<<1, 32, 0, s2>>>(alpha, lsig);
    sq_kernel<<<(BB*NN*CC + 127)/128, 128, 0, s2>>>(x);
    bias_kernel<<<dim3(NN/64, NN/64, BB*HH), 256, 0, s2>>>(x);
    cudaEventRecord(evJoinB, s2);     // bias + uniform flag ready

    // main stream: h conversion (critical path), then QKV (needs weights)
    convert_h_kernel<<<(BB*NN*DM_/8 + 255)/256, 256>>>(h);
    cudaStreamWaitEvent(0, evJoinW, 0);
    qkv_gemm<<<dim3(DM_/128, (BB*NN)/128, 3), 256, GSMEM>>>(bq, bk, bv);

    cudaStreamWaitEvent(0, evJoinB, 0);
    attn_hmma<<<dim3(NN/128, BB*HH), 256, ASMEM>>>();

    out_gemm<<<dim3(DM_/128, (BB*NN)/128), 256, GSMEM>>>(bo, out);
}

// round 16
// speedup vs baseline: 1.2322x; 1.0718x over previous
#include <cuda_runtime.h>
#include <cuda_fp16.h>
#include <math.h>
#include <stdint.h>

#define BB  4
#define NN  1024
#define DM_ 512
#define HH  8
#define CC  3
#define DC_ 16
#define DK_ 64
#define XW  (CC*DC_)
#define LOG2E 1.44269504088896340736f
#define SOFTMAX_SHIFT 8.0f

// ---------------- device scratch (16B-aligned for vector ld/st) ------------
__device__ __align__(16) __half g_h16[(size_t)BB*NN*DM_];
__device__ __align__(16) __half g_Wq16[DM_*DM_];
__device__ __align__(16) __half g_Wk16[DM_*DM_];
__device__ __align__(16) __half g_Wv16[DM_*DM_];
__device__ __align__(16) __half g_Wo16[DM_*DM_];
__device__ __align__(16) __half g_Q16[(size_t)BB*HH*NN*DK_];
__device__ __align__(16) __half g_K16[(size_t)BB*HH*NN*DK_];
__device__ __align__(16) __half g_V16[(size_t)BB*HH*NN*DK_];
__device__ __align__(16) __half g_AO16[(size_t)BB*NN*DM_];
__device__ __align__(16) float  g_bias[(size_t)BB*HH*NN*NN];   // bias*log2e - SHIFT
__device__ __align__(16) float  g_sq[BB*NN*CC];
__device__ __align__(16) float  g_alpha[HH*CC];
__device__ __align__(16) float  g_gcoef[HH*CC];
__device__ int    g_uniform;

// ---------------- helpers ----------------
__device__ __forceinline__ uint32_t smem_u32(const void* p) {
    uint32_t a;
    asm("{ .reg .u64 t; cvta.to.shared.u64 t, %1; cvt.u32.u64 %0, t; }" : "=r"(a) : "l"(p));
    return a;
}
__device__ __forceinline__ uint32_t swz(uint32_t o) { return o ^ ((o >> 3) & 0x70); }

__device__ __forceinline__ void mma16816(float* d, const uint32_t* a, const uint32_t* b) {
    asm volatile("mma.sync.aligned.m16n8k16.row.col.f32.f16.f16.f32 "
        "{%0,%1,%2,%3}, {%4,%5,%6,%7}, {%8,%9}, {%0,%1,%2,%3};"
        : "+f"(d[0]), "+f"(d[1]), "+f"(d[2]), "+f"(d[3])
        : "r"(a[0]), "r"(a[1]), "r"(a[2]), "r"(a[3]), "r"(b[0]), "r"(b[1]));
}
__device__ __forceinline__ void ldm_x4(uint32_t* r, uint32_t addr) {
    asm volatile("ldmatrix.sync.aligned.m8n8.x4.shared.b16 {%0,%1,%2,%3}, [%4];"
        : "=r"(r[0]), "=r"(r[1]), "=r"(r[2]), "=r"(r[3]) : "r"(addr));
}
__device__ __forceinline__ void ldm_x4_t(uint32_t* r, uint32_t addr) {
    asm volatile("ldmatrix.sync.aligned.m8n8.x4.trans.shared.b16 {%0,%1,%2,%3}, [%4];"
        : "=r"(r[0]), "=r"(r[1]), "=r"(r[2]), "=r"(r[3]) : "r"(addr));
}
__device__ __forceinline__ void cp16(uint32_t saddr, const void* gptr) {
    asm volatile("cp.async.cg.shared.global [%0], [%1], 16;" :: "r"(saddr), "l"(gptr));
}
#define CP_COMMIT() asm volatile("cp.async.commit_group;" ::: "memory")
#define CP_WAIT1()  asm volatile("cp.async.wait_group 1;" ::: "memory")
#define CP_WAIT0()  asm volatile("cp.async.wait_group 0;" ::: "memory")

// ---------------- small prep kernels ----------------
__global__ void prep_coef_kernel(const float* __restrict__ alpha, const float* __restrict__ lsig) {
    int i = threadIdx.x;
    int ok = 1;
    if (i < HH*CC) {
        float a = alpha[i], l = lsig[i];
        float s = expf(l);
        if (s < 1e-4f) s = 1e-4f;
        g_gcoef[i] = 1.0f / (2.0f * s * s);
        g_alpha[i] = a;
        ok = (a == alpha[i % CC]) && (l == lsig[i % CC]);
    }
    int uni = __all_sync(0xffffffffu, ok);
    if (i == 0) g_uniform = uni;
}

__global__ void sq_kernel(const float* __restrict__ x) {
    int t = blockIdx.x * blockDim.x + threadIdx.x;
    if (t >= BB*NN*CC) return;
    int c = t % CC; int bn = t / CC;
    const float* p = x + (size_t)bn * XW + c * DC_;
    float s = 0.f;
#pragma unroll
    for (int d = 0; d < DC_; d++) s += p[d] * p[d];
    g_sq[t] = s;
}

__device__ __forceinline__ void cvt8(const float* __restrict__ src, __half* __restrict__ dst) {
    float4 a = *(const float4*)src;
    float4 b = *(const float4*)(src + 4);
    __half2 r[4];
    r[0] = __floats2half2_rn(a.x, a.y);
    r[1] = __floats2half2_rn(a.z, a.w);
    r[2] = __floats2half2_rn(b.x, b.y);
    r[3] = __floats2half2_rn(b.z, b.w);
    *(uint4*)dst = *(uint4*)r;
}

__global__ void convert_h_kernel(const float* __restrict__ h) {
    int i = blockIdx.x * blockDim.x + threadIdx.x;
    if (i < BB*NN*DM_/8) cvt8(h + (size_t)i*8, g_h16 + (size_t)i*8);
}

__global__ void convert_w_kernel(const float* __restrict__ wq, const float* __restrict__ wk,
                                 const float* __restrict__ wv, const float* __restrict__ wo) {
    int i = blockIdx.x * blockDim.x + threadIdx.x;
    if (i < DM_*DM_/8) {
        cvt8(wq + i*8, g_Wq16 + i*8);
        cvt8(wk + i*8, g_Wk16 + i*8);
        cvt8(wv + i*8, g_Wv16 + i*8);
        cvt8(wo + i*8, g_Wo16 + i*8);
    }
}

// ---------------- geodesic bias (fp32; stores bias*log2e - SHIFT) ----------
__global__ __launch_bounds__(256, 3)
void bias_kernel(const float* __restrict__ x) {
    __shared__ float Xi[64][49];
    __shared__ float Xj[64][49];
    __shared__ float sqi[64][3];
    __shared__ float sqj[64][3];

    const int bh = blockIdx.z;
    const int h2 = bh & (HH-1);
    const int b2 = bh >> 3;
    if (g_uniform && h2 > 0) return;

    const int i0 = blockIdx.y * 64, j0 = blockIdx.x * 64;
    const int tid = threadIdx.x;
    const int tx = tid & 15, ty = tid >> 4;

    const float* xb = x + (size_t)b2 * NN * XW;
#pragma unroll
    for (int t = 0; t < 12; t++) {
        int idx = tid + t * 256;
        int row = idx / XW, col = idx % XW;
        Xi[row][col] = xb[(size_t)(i0 + row) * XW + col];
        Xj[row][col] = xb[(size_t)(j0 + row) * XW + col];
    }
    if (tid < 192) {
        int row = tid / 3, c = tid % 3;
        sqi[row][c] = g_sq[((size_t)b2 * NN + i0 + row) * CC + c];
        sqj[row][c] = g_sq[((size_t)b2 * NN + j0 + row) * CC + c];
    }
    __syncthreads();

    float bsum[4][4] = {};

#pragma unroll
    for (int cm = 0; cm < CC; cm++) {
        const float A = g_alpha[h2*CC + cm] * LOG2E;
        const float G = g_gcoef[h2*CC + cm] * LOG2E;

        float inner[4][4] = {};
#pragma unroll
        for (int d = 0; d < DC_; d++) {
            float xi[4], xj[4];
#pragma unroll
            for (int r = 0; r < 4; r++) xi[r] = Xi[4*ty + r][cm*DC_ + d];
#pragma unroll
            for (int c = 0; c < 4; c++) xj[c] = Xj[4*tx + c][cm*DC_ + d];
#pragma unroll
            for (int r = 0; r < 4; r++)
#pragma unroll
                for (int c = 0; c < 4; c++)
                    inner[r][c] = fmaf(xi[r], xj[c], inner[r][c]);
        }
#pragma unroll
        for (int r = 0; r < 4; r++) {
            float si = sqi[4*ty + r][cm];
#pragma unroll
            for (int c = 0; c < 4; c++) {
                float dd = fmaxf(si + sqj[4*tx + c][cm] - 2.f * inner[r][c], 0.f);
                bsum[r][c] = fmaf(A, exp2f(-dd * G), bsum[r][c]);
            }
        }
    }

    float* outp = g_bias + (size_t)(b2*HH + h2) * NN * NN;
#pragma unroll
    for (int r = 0; r < 4; r++) {
        float4 res = make_float4(bsum[r][0] - SOFTMAX_SHIFT, bsum[r][1] - SOFTMAX_SHIFT,
                                 bsum[r][2] - SOFTMAX_SHIFT, bsum[r][3] - SOFTMAX_SHIFT);
        *(float4*)(outp + (size_t)(i0 + 4*ty + r) * NN + j0 + 4*tx) = res;
    }
}

// ---------------- HMMA GEMM (128x128 block, K=512, cp.async 3-stage) -------
#define GSMEM 98304

__device__ __forceinline__ void gemm_load_stage(const __half* __restrict__ A,
                                                const __half* __restrict__ W,
                                                uint32_t sb, int m0, int o0,
                                                int kt, int stage, int tid) {
    const uint32_t base = sb + (uint32_t)stage * 32768u;
#pragma unroll
    for (int i = 0; i < 4; i++) {
        int idx = tid + i * 256, row = idx >> 3, seg = idx & 7;
        uint32_t sw = swz((uint32_t)(row * 128 + seg * 16));
        cp16(base + sw,          A + (size_t)(m0 + row) * DM_ + kt*64 + seg*8);
        cp16(base + 16384 + sw,  W + (size_t)(o0 + row) * DM_ + kt*64 + seg*8);
    }
}

__device__ __forceinline__ void hmma_mainloop(const __half* __restrict__ A,
                                              const __half* __restrict__ W,
                                              char* smem, int m0, int o0,
                                              float acc[4][4][4]) {
    const int tid = threadIdx.x;
    const int lane = tid & 31, wid = tid >> 5;
    const int wm = wid >> 2, wn = wid & 3;
    const uint32_t sb = smem_u32(smem);

    gemm_load_stage(A, W, sb, m0, o0, 0, 0, tid); CP_COMMIT();
    gemm_load_stage(A, W, sb, m0, o0, 1, 1, tid); CP_COMMIT();

    for (int kt = 0; kt < 8; kt++) {
        CP_WAIT1();
        __syncthreads();
        const uint32_t abase = sb + (uint32_t)(kt % 3) * 32768u;
        const uint32_t bbase = abase + 16384;
#pragma unroll
        for (int ks = 0; ks < 4; ks++) {
            uint32_t af[4][4];
#pragma unroll
            for (int mt = 0; mt < 4; mt++)
                ldm_x4(af[mt], abase + swz((uint32_t)((wm*64 + mt*16 + (lane & 15)) * 128
                                                      + ks*32 + ((lane >> 4) & 1) * 16)));
#pragma unroll
            for (int np = 0; np < 2; np++) {
                uint32_t bf[4];
                ldm_x4(bf, bbase + swz((uint32_t)((wn*32 + np*16 + (lane & 7) + ((lane >> 4) & 1)*8) * 128
                                                  + ks*32 + ((lane >> 3) & 1) * 16)));
#pragma unroll
                for (int mt = 0; mt < 4; mt++) {
                    mma16816(acc[mt][np*2],     af[mt], bf);
                    mma16816(acc[mt][np*2 + 1], af[mt], bf + 2);
                }
            }
        }
        if (kt < 6) gemm_load_stage(A, W, sb, m0, o0, kt + 2, (kt + 2) % 3, tid);
        CP_COMMIT();
    }
}

__global__ __launch_bounds__(256, 2)
void qkv_gemm(const float* __restrict__ bq, const float* __restrict__ bk, const float* __restrict__ bv) {
    extern __shared__ char smem[];
    const int z = blockIdx.z;
    const __half* W = (z == 0) ? g_Wq16 : ((z == 1) ? g_Wk16 : g_Wv16);
    const float* bias = (z == 0) ? bq : ((z == 1) ? bk : bv);
    __half* OUT = (z == 0) ? g_Q16 : ((z == 1) ? g_K16 : g_V16);
    const float scale = (z == 0) ? (0.125f * LOG2E) : 1.0f;
    const int m0 = blockIdx.y * 128, o0 = blockIdx.x * 128;

    float acc[4][4][4] = {};
    hmma_mainloop(g_h16, W, smem, m0, o0, acc);

    const int lane = threadIdx.x & 31, wid = threadIdx.x >> 5;
    const int wm = wid >> 2, wn = wid & 3;
    const int g = lane >> 2, t2 = (lane & 3) * 2;
#pragma unroll
    for (int mt = 0; mt < 4; mt++) {
#pragma unroll
        for (int nt = 0; nt < 4; nt++) {
            int o = o0 + wn*32 + nt*8 + t2;
            int hd = o >> 6, dk0 = o & 63;
            float b0 = bias[o], b1 = bias[o + 1];
#pragma unroll
            for (int half = 0; half < 2; half++) {
                int m = m0 + wm*64 + mt*16 + g + half*8;
                int b2 = m >> 10, n2 = m & 1023;
                float v0 = (acc[mt][nt][half*2]     + b0) * scale;
                float v1 = (acc[mt][nt][half*2 + 1] + b1) * scale;
                __half2 hh = __floats2half2_rn(v0, v1);
                *(__half2*)(OUT + (((size_t)(b2*HH + hd)) * NN + n2) * DK_ + dk0) = hh;
            }
        }
    }
}

__global__ __launch_bounds__(256, 2)
void out_gemm(const float* __restrict__ bo, float* __restrict__ out) {
    extern __shared__ char smem[];
    const int m0 = blockIdx.y * 128, o0 = blockIdx.x * 128;

    float acc[4][4][4] = {};
    hmma_mainloop(g_AO16, g_Wo16, smem, m0, o0, acc);

    const int lane = threadIdx.x & 31, wid = threadIdx.x >> 5;
    const int wm = wid >> 2, wn = wid & 3;
    const int g = lane >> 2, t2 = (lane & 3) * 2;
#pragma unroll
    for (int mt = 0; mt < 4; mt++) {
#pragma unroll
        for (int nt = 0; nt < 4; nt++) {
            int o = o0 + wn*32 + nt*8 + t2;
            float b0 = bo[o], b1 = bo[o + 1];
#pragma unroll
            for (int half = 0; half < 2; half++) {
                int m = m0 + wm*64 + mt*16 + g + half*8;
                float* dst = out + (size_t)m * DM_ + o;
                dst[0] = acc[mt][nt][half*2]     + b0;
                dst[1] = acc[mt][nt][half*2 + 1] + b1;
            }
        }
    }
}

// ---------------- HMMA flash attention, shifted softmax (no running max) ---
#define ASMEM 81920

__device__ __forceinline__ void attn_load_kv(const __half* __restrict__ Kb,
                                             const __half* __restrict__ Vb,
                                             uint32_t sb, int j0, int stage, int tid) {
    const uint32_t kbase = sb + 16384u + (uint32_t)stage * 32768u;
#pragma unroll
    for (int i = 0; i < 4; i++) {
        int idx = tid + i * 256, row = idx >> 3, seg = idx & 7;
        uint32_t sw = swz((uint32_t)(row * 128 + seg * 16));
        cp16(kbase + sw,          Kb + (size_t)(j0 + row) * DK_ + seg * 8);
        cp16(kbase + 16384 + sw,  Vb + (size_t)(j0 + row) * DK_ + seg * 8);
    }
}

__global__ __launch_bounds__(256, 2)
void attn_hmma() {
    extern __shared__ char smem[];
    const uint32_t sb = smem_u32(smem);
    const int tid = threadIdx.x;
    const int lane = tid & 31, w = tid >> 5;
    const int g = lane >> 2, t2 = (lane & 3) * 2;

    const int bh = blockIdx.y;
    const int b2 = bh >> 3, h2 = bh & 7;
    const int i0 = blockIdx.x * 128;
    const int heff = g_uniform ? 0 : h2;

    const __half* Kb = g_K16 + (size_t)bh * NN * DK_;
    const __half* Vb = g_V16 + (size_t)bh * NN * DK_;

    attn_load_kv(Kb, Vb, sb, 0, 0, tid); CP_COMMIT();

    const __half* Qg = g_Q16 + ((size_t)bh * NN + i0) * DK_;
#pragma unroll
    for (int i = 0; i < 4; i++) {
        int idx = tid + i * 256, row = idx >> 3, seg = idx & 7;
        uint32_t sw = swz((uint32_t)(row * 128 + seg * 16));
        *(uint4*)(smem + sw) = *(const uint4*)(Qg + (size_t)row * DK_ + seg * 8);
    }
    __syncthreads();

    uint32_t qa[4][4];
#pragma unroll
    for (int ks = 0; ks < 4; ks++)
        ldm_x4(qa[ks], sb + swz((uint32_t)((w*16 + (lane & 15)) * 128
                                           + ks*32 + ((lane >> 4) & 1) * 16)));

    float l1 = 0.f, l2 = 0.f;
    float o_[8][4] = {};

    const float* Bg = g_bias + ((size_t)(b2*HH + heff) * NN + i0) * NN;

    for (int jt = 0; jt < 8; jt++) {
        const int j0 = jt * 128;
        CP_WAIT0();
        __syncthreads();
        if (jt < 7) { attn_load_kv(Kb, Vb, sb, (jt + 1) * 128, (jt + 1) & 1, tid); CP_COMMIT(); }

        const uint32_t KOFF = 16384u + (uint32_t)(jt & 1) * 32768u;
        const uint32_t VOFF = KOFF + 16384u;

        // init S accumulators with (bias*log2e - SHIFT)
        float sf[16][4];
        const float* bp1 = Bg + (size_t)(16*w + g) * NN + j0 + t2;
        const float* bp2 = bp1 + 8 * NN;
#pragma unroll
        for (int nt = 0; nt < 16; nt++) {
            float2 bv1 = *(const float2*)(bp1 + nt*8);
            float2 bv2 = *(const float2*)(bp2 + nt*8);
            sf[nt][0] = bv1.x; sf[nt][1] = bv1.y;
            sf[nt][2] = bv2.x; sf[nt][3] = bv2.y;
        }

        // S = bias + Q @ K^T  (base-2 logits, pre-shifted)
#pragma unroll
        for (int np = 0; np < 8; np++) {
#pragma unroll
            for (int ks = 0; ks < 4; ks++) {
                uint32_t bf[4];
                ldm_x4(bf, sb + KOFF + swz((uint32_t)((np*16 + (lane & 7) + ((lane >> 4) & 1)*8) * 128
                                                      + ks*32 + ((lane >> 3) & 1) * 16)));
                mma16816(sf[np*2],     qa[ks], bf);
                mma16816(sf[np*2 + 1], qa[ks], bf + 2);
            }
        }

        // P = 2^S directly (no max subtraction), interleaved with PV MMA
#pragma unroll
        for (int kk = 0; kk < 8; kk++) {
            float e00 = exp2f(sf[2*kk][0]),   e01 = exp2f(sf[2*kk][1]);
            float e02 = exp2f(sf[2*kk][2]),   e03 = exp2f(sf[2*kk][3]);
            float e10 = exp2f(sf[2*kk+1][0]), e11 = exp2f(sf[2*kk+1][1]);
            float e12 = exp2f(sf[2*kk+1][2]), e13 = exp2f(sf[2*kk+1][3]);
            l1 += e00 + e01 + e10 + e11;
            l2 += e02 + e03 + e12 + e13;

            uint32_t pa[4];
            {
                __half2 h0 = __floats2half2_rn(e00, e01);
                __half2 h1 = __floats2half2_rn(e02, e03);
                __half2 h2_ = __floats2half2_rn(e10, e11);
                __half2 h3 = __floats2half2_rn(e12, e13);
                pa[0] = *(uint32_t*)&h0; pa[1] = *(uint32_t*)&h1;
                pa[2] = *(uint32_t*)&h2_; pa[3] = *(uint32_t*)&h3;
            }
#pragma unroll
            for (int dp = 0; dp < 4; dp++) {
                uint32_t bf[4];
                ldm_x4_t(bf, sb + VOFF + swz((uint32_t)((kk*16 + (lane & 7) + ((lane >> 3) & 1)*8) * 128
                                                        + dp*32 + ((lane >> 4) & 1) * 16)));
                mma16816(o_[dp*2],     pa, bf);
                mma16816(o_[dp*2 + 1], pa, bf + 2);
            }
        }
    }

    // single cross-lane l reduction at the end (additive across tiles)
    l1 += __shfl_xor_sync(0xffffffffu, l1, 1);
    l1 += __shfl_xor_sync(0xffffffffu, l1, 2);
    l2 += __shfl_xor_sync(0xffffffffu, l2, 1);
    l2 += __shfl_xor_sync(0xffffffffu, l2, 2);

    // epilogue
    float i1 = 1.0f / l1, i2 = 1.0f / l2;
    __half* dst1 = g_AO16 + ((size_t)b2 * NN + i0 + 16*w + g)     * DM_ + h2*DK_ + t2;
    __half* dst2 = g_AO16 + ((size_t)b2 * NN + i0 + 16*w + g + 8) * DM_ + h2*DK_ + t2;
#pragma unroll
    for (int dt = 0; dt < 8; dt++) {
        *(__half2*)(dst1 + dt*8) = __floats2half2_rn(o_[dt][0] * i1, o_[dt][1] * i1);
        *(__half2*)(dst2 + dt*8) = __floats2half2_rn(o_[dt][2] * i2, o_[dt][3] * i2);
    }
}

// ---------------- launcher ----------------
extern "C" void kernel_launch(void* const* d_in, const int* in_sizes, int n_in,
                              void* d_out, int out_size) {
    const float* h    = (const float*)d_in[0];
    const float* x    = (const float*)d_in[1];
    const float* Wq   = (const float*)d_in[2];
    const float* bq   = (const float*)d_in[3];
    const float* Wk   = (const float*)d_in[4];
    const float* bk   = (const float*)d_in[5];
    const float* Wv   = (const float*)d_in[6];
    const float* bv   = (const float*)d_in[7];
    const float* Wo   = (const float*)d_in[8];
    const float* bo   = (const float*)d_in[9];
    const float* alpha= (const float*)d_in[10];
    const float* lsig = (const float*)d_in[11];
    float* out = (float*)d_out;

    static cudaStream_t s2 = nullptr;
    static cudaEvent_t evFork = nullptr, evJoinW = nullptr, evJoinB = nullptr;
    if (s2 == nullptr) {
        cudaStreamCreateWithFlags(&s2, cudaStreamNonBlocking);
        cudaEventCreateWithFlags(&evFork, cudaEventDisableTiming);
        cudaEventCreateWithFlags(&evJoinW, cudaEventDisableTiming);
        cudaEventCreateWithFlags(&evJoinB, cudaEventDisableTiming);
    }

    cudaFuncSetAttribute(qkv_gemm, cudaFuncAttributeMaxDynamicSharedMemorySize, GSMEM);
    cudaFuncSetAttribute(out_gemm, cudaFuncAttributeMaxDynamicSharedMemorySize, GSMEM);
    cudaFuncSetAttribute(attn_hmma, cudaFuncAttributeMaxDynamicSharedMemorySize, ASMEM);

    // fork: side stream converts weights, then runs the bias chain
    cudaEventRecord(evFork, 0);
    cudaStreamWaitEvent(s2, evFork, 0);
    convert_w_kernel<<<(DM_*DM_/8 + 255)/256, 256, 0, s2>>>(Wq, Wk, Wv, Wo);
    cudaEventRecord(evJoinW, s2);     // weights ready
    prep_coef_kernel<<<1, 32, 0, s2>>>(alpha, lsig);
    sq_kernel<<<(BB*NN*CC + 127)/128, 128, 0, s2>>>(x);
    bias_kernel<<<dim3(NN/64, NN/64, BB*HH), 256, 0, s2>>>(x);
    cudaEventRecord(evJoinB, s2);     // bias + uniform flag ready

    // main stream: h conversion (critical path), then QKV (needs weights)
    convert_h_kernel<<<(BB*NN*DM_/8 + 255)/256, 256>>>(h);
    cudaStreamWaitEvent(0, evJoinW, 0);
    qkv_gemm<<<dim3(DM_/128, (BB*NN)/128, 3), 256, GSMEM>>>(bq, bk, bv);

    cudaStreamWaitEvent(0, evJoinB, 0);
    attn_hmma<<<dim3(NN/128, BB*HH), 256, ASMEM>>>();

    out_gemm<<<dim3(DM_/128, (BB*NN)/128), 256, GSMEM>>>(bo, out);
}